// round 5
// baseline (speedup 1.0000x reference)
#include <cuda_runtime.h>
#include <cuda_bf16.h>
#include <cstdint>

// ---------------------------------------------------------------------------
// Problem constants
// ---------------------------------------------------------------------------
#define BATCH   8192
#define SEQ     8
#define HID     2048
#define NEXP    64
#define TOPK    8
#define ROWSTR  (SEQ * HID)

// GEMM config: BM=64 so two CTAs fit per SM (96KB smem each)
#define BM      64
#define KT      64                 // k-tile (f32 elements)
#define KSPL    2
#define KHALF   (HID / KSPL)       // 1024
#define NT      (KHALF / KT)       // 16 tiles per split

// smem plane sizes (bf16, 128B per row)
#define A_PL    8192               // 64 rows x 128B
#define B_PL    8192               // 64 rows x 128B
#define ABUF    (3 * A_PL)
#define BBUF    (3 * B_PL)
#define STAGE   (ABUF + BBUF)      // 49152
#define SM_ALLOC (2 * STAGE + 1024)   // 99328 -> 2 CTAs/SM

// Router config
#define RBLK    256                // blocks
#define RTHR    1024               // threads (32 warps = 32 rows per block)

// Scratch (no allocation allowed)
__device__ float    g_partial[KSPL][BATCH * NEXP];   // 4 MB
__device__ float    g_bimp[RBLK][NEXP];
__device__ int      g_bcnt[RBLK][NEXP];
__device__ unsigned g_done;

// ---------------------------------------------------------------------------
// helpers
// ---------------------------------------------------------------------------
__device__ __forceinline__ uint32_t smem_to_u32(const void* p) {
    uint32_t a;
    asm("{ .reg .u64 t; cvta.to.shared.u64 t, %1; cvt.u32.u64 %0, t; }"
        : "=r"(a) : "l"(p));
    return a;
}
__device__ __forceinline__ void ldsm4(uint32_t* r, uint32_t addr) {
    asm volatile("ldmatrix.sync.aligned.m8n8.x4.shared.b16 {%0,%1,%2,%3}, [%4];"
                 : "=r"(r[0]), "=r"(r[1]), "=r"(r[2]), "=r"(r[3]) : "r"(addr));
}
__device__ __forceinline__ void mma16816(float* d, const uint32_t* a,
                                         const uint32_t* b) {
    asm volatile(
        "mma.sync.aligned.m16n8k16.row.col.f32.bf16.bf16.f32 "
        "{%0,%1,%2,%3}, {%4,%5,%6,%7}, {%8,%9}, {%0,%1,%2,%3};"
        : "+f"(d[0]), "+f"(d[1]), "+f"(d[2]), "+f"(d[3])
        : "r"(a[0]), "r"(a[1]), "r"(a[2]), "r"(a[3]), "r"(b[0]), "r"(b[1]));
}
__device__ __forceinline__ uint32_t pack_bf16(float lo, float hi) {
    uint32_t r;
    asm("cvt.rn.bf16x2.f32 %0, %1, %2;" : "=r"(r) : "f"(hi), "f"(lo));
    return r;
}
// fp32 -> 3x bf16 split: h + m + l reproduces x to ~2^-26 relative
__device__ __forceinline__ void split3(float x, float y,
                                       uint32_t& h, uint32_t& m, uint32_t& l) {
    h = pack_bf16(x, y);
    float hx = __uint_as_float(h << 16);
    float hy = __uint_as_float(h & 0xffff0000u);
    float rx = x - hx, ry = y - hy;
    m = pack_bf16(rx, ry);
    float mx = __uint_as_float(m << 16);
    float my = __uint_as_float(m & 0xffff0000u);
    l = pack_bf16(rx - mx, ry - my);
}
__device__ __forceinline__ void sts64(uint32_t addr, uint32_t a, uint32_t b) {
    asm volatile("st.shared.v2.b32 [%0], {%1, %2};"
                 :: "r"(addr), "r"(a), "r"(b) : "memory");
}

// ---------------------------------------------------------------------------
// Kernel 1: HMMA logits GEMM, fp32 emulated with bf16 3-split (6 products).
// D[64,64] per (m-tile, k-split). 256 threads = 8 warps = 4(M) x 2(N).
// ---------------------------------------------------------------------------
__global__ void __launch_bounds__(256, 2)
gemm_tc(const float* __restrict__ hs, const float* __restrict__ gw) {
    extern __shared__ char smem_raw[];
    const uint32_t sb = (smem_to_u32(smem_raw) + 1023u) & ~1023u;

    const int tid  = threadIdx.x;
    const int wid  = tid >> 5;
    const int lane = tid & 31;
    const int m0   = blockIdx.x * BM;
    const int sp   = blockIdx.y;
    const int k0   = sp * KHALF;

    if (blockIdx.x == 0 && sp == 0 && tid == 0) g_done = 0u;

    // ---- f32 staging in regs ----
    float4 ar[4], br[4];
#define LOAD_A(t) do {                                                        \
    int kk = k0 + (t) * KT;                                                   \
    _Pragma("unroll")                                                         \
    for (int i = 0; i < 4; i++) {                                             \
        int lin = tid + i * 256; int row = lin >> 4; int c4 = lin & 15;       \
        ar[i] = *(const float4*)(hs + (size_t)(m0 + row) * ROWSTR + kk + c4 * 4); \
    } } while (0)
#define LOAD_B(t) do {                                                        \
    int kk = k0 + (t) * KT;                                                   \
    _Pragma("unroll")                                                         \
    for (int i = 0; i < 4; i++) {                                             \
        int lin = tid + i * 256; int row = lin >> 4; int c4 = lin & 15;       \
        br[i] = *(const float4*)(gw + (size_t)row * HID + kk + c4 * 4);       \
    } } while (0)

    LOAD_A(0); LOAD_B(0);

    // ---- per-warp ldmatrix bases (unswizzled) + swizzle masks ----
    const int mrow = (wid & 3) * 16;       // warp M offset within 64
    const int nrow = (wid >> 2) * 32;      // warp N offset within 64

    uint32_t abase, amask;
    {
        int row = mrow + (lane & 15);
        abase = (uint32_t)(row * 128 + (lane >> 4) * 16);
        amask = (uint32_t)((row & 7) << 4);
    }
    uint32_t bbase[2], bmask[2];
#pragma unroll
    for (int nt = 0; nt < 2; nt++) {
        int mat = lane >> 3, r = lane & 7;
        int n  = nrow + nt * 16 + (mat >> 1) * 8 + r;
        int kb = (mat & 1) * 16;
        bbase[nt] = (uint32_t)(n * 128 + kb);
        bmask[nt] = (uint32_t)((n & 7) << 4);
    }

    float acc[4][4];
#pragma unroll
    for (int b = 0; b < 4; b++)
#pragma unroll
        for (int c = 0; c < 4; c++) acc[b][c] = 0.0f;

    const int pa[6] = {0, 0, 1, 0, 2, 1};   // hh, hm, mh, hl, lh, mm
    const int pb[6] = {0, 1, 0, 2, 0, 1};

    for (int t = 0; t < NT; t++) {
        const uint32_t stg   = sb + (uint32_t)(t & 1) * STAGE;
        const uint32_t aBase = stg;
        const uint32_t bBase = stg + ABUF;

        // convert + swizzled store: A (4 float4 -> 3 planes)
#pragma unroll
        for (int i = 0; i < 4; i++) {
            int lin = tid + i * 256; int row = lin >> 4; int c4 = lin & 15;
            uint32_t off = (uint32_t)(row * 128 + c4 * 8);
            uint32_t sw  = off ^ ((off >> 3) & 0x70u);
            uint32_t h0, mm0, l0, h1, mm1, l1;
            split3(ar[i].x, ar[i].y, h0, mm0, l0);
            split3(ar[i].z, ar[i].w, h1, mm1, l1);
            sts64(aBase + sw,            h0,  h1);
            sts64(aBase + A_PL + sw,     mm0, mm1);
            sts64(aBase + 2 * A_PL + sw, l0,  l1);
        }
        // convert + swizzled store: B
#pragma unroll
        for (int i = 0; i < 4; i++) {
            int lin = tid + i * 256; int row = lin >> 4; int c4 = lin & 15;
            uint32_t off = (uint32_t)(row * 128 + c4 * 8);
            uint32_t sw  = off ^ ((off >> 3) & 0x70u);
            uint32_t h0, mm0, l0, h1, mm1, l1;
            split3(br[i].x, br[i].y, h0, mm0, l0);
            split3(br[i].z, br[i].w, h1, mm1, l1);
            sts64(bBase + sw,            h0,  h1);
            sts64(bBase + B_PL + sw,     mm0, mm1);
            sts64(bBase + 2 * B_PL + sw, l0,  l1);
        }
        __syncthreads();

        // prefetch next tile's f32 (overlaps with MMA below)
        if (t + 1 < NT) { LOAD_A(t + 1); LOAD_B(t + 1); }

        // compute: 4 k16 chunks x (9 ldmatrix.x4 + 24 mma) per warp
#pragma unroll
        for (int kc = 0; kc < 4; kc++) {
            uint32_t af[3][4];
            uint32_t bf[3][2][4];
#pragma unroll
            for (int p = 0; p < 3; p++) {
                ldsm4(af[p], aBase + p * A_PL + ((abase + kc * 32) ^ amask));
#pragma unroll
                for (int nt = 0; nt < 2; nt++)
                    ldsm4(bf[p][nt],
                          bBase + p * B_PL + ((bbase[nt] + kc * 32) ^ bmask[nt]));
            }
#pragma unroll
            for (int pr = 0; pr < 6; pr++) {
#pragma unroll
                for (int nt = 0; nt < 2; nt++) {
                    mma16816(acc[nt * 2 + 0], af[pa[pr]], &bf[pb[pr]][nt][0]);
                    mma16816(acc[nt * 2 + 1], af[pa[pr]], &bf[pb[pr]][nt][2]);
                }
            }
        }
        __syncthreads();
    }

    // ---- epilogue: warp writes its 16x32 f32 tile to split partials ----
    const int gr = m0 + mrow + (lane >> 2);
    const int gc = nrow + (lane & 3) * 2;
#pragma unroll
    for (int n8 = 0; n8 < 4; n8++) {
        int col = gc + n8 * 8;
        *(float2*)&g_partial[sp][(size_t)gr * NEXP + col] =
            make_float2(acc[n8][0], acc[n8][1]);
        *(float2*)&g_partial[sp][(size_t)(gr + 8) * NEXP + col] =
            make_float2(acc[n8][2], acc[n8][3]);
    }
#undef LOAD_A
#undef LOAD_B
}

// ---------------------------------------------------------------------------
// Kernel 2: warp-per-row softmax + top-8 + weights. Importance/load reduced
// per-block into private global slots (no contended atomics); last block
// (ticket) computes aux_loss.
// ---------------------------------------------------------------------------
__global__ void __launch_bounds__(RTHR)
router_kernel(float* __restrict__ out) {
    __shared__ float s_pr[RTHR / 32][NEXP];   // per-warp probs, 8KB
    __shared__ int   s_cnt[NEXP];
    __shared__ int   s_last;
    const int tid  = threadIdx.x;
    const int lane = tid & 31;
    const int w    = tid >> 5;                // warp = local row
    if (tid < NEXP) s_cnt[tid] = 0;
    __syncthreads();

    const int row = blockIdx.x * (RTHR / 32) + w;

    // sum split-K partials; lane owns experts lane, lane+32
    const float* p0p = &g_partial[0][(size_t)row * NEXP];
    const float* p1p = &g_partial[1][(size_t)row * NEXP];
    float l0 = p0p[lane] + p1p[lane];
    float l1 = p0p[lane + 32] + p1p[lane + 32];

    // softmax over 64
    float m = fmaxf(l0, l1);
#pragma unroll
    for (int off = 16; off; off >>= 1)
        m = fmaxf(m, __shfl_xor_sync(0xffffffffu, m, off));
    float p0 = __expf(l0 - m);
    float p1 = __expf(l1 - m);
    float sm = p0 + p1;
#pragma unroll
    for (int off = 16; off; off >>= 1)
        sm += __shfl_xor_sync(0xffffffffu, sm, off);
    float inv = 1.0f / sm;
    p0 *= inv;
    p1 *= inv;

    // stash probs for block-level importance reduction (plain stores)
    s_pr[w][lane]      = p0;
    s_pr[w][lane + 32] = p1;

    // top-8 via iterated warp argmax (tie -> smaller index)
    bool sel0 = false, sel1 = false;
    float wsum = 0.0f, myv = 0.0f;
    int myi = 0;
#pragma unroll
    for (int it = 0; it < TOPK; it++) {
        float cv = sel0 ? -1.0f : p0;
        int   ci = lane;
        if (!sel1 && p1 > cv) { cv = p1; ci = lane + 32; }
#pragma unroll
        for (int off = 16; off; off >>= 1) {
            float ov = __shfl_xor_sync(0xffffffffu, cv, off);
            int   oi = __shfl_xor_sync(0xffffffffu, ci, off);
            if (ov > cv || (ov == cv && oi < ci)) { cv = ov; ci = oi; }
        }
        wsum += cv;
        if (ci == lane)           sel0 = true;
        else if (ci == lane + 32) sel1 = true;
        if (lane == it) { myv = cv; myi = ci; }
        if (lane == 0)  atomicAdd(&s_cnt[ci], 1);
    }

    float invw = 1.0f / fmaxf(wsum, 1e-8f);
    if (lane < TOPK) {
        out[(size_t)row * TOPK + lane] = (float)myi;
        out[(size_t)BATCH * TOPK + (size_t)row * TOPK + lane] = myv * invw;
    }

    __syncthreads();

    // block importance: expert e summed over 32 warps
    if (tid < NEXP) {
        float si = 0.0f;
#pragma unroll
        for (int ww = 0; ww < RTHR / 32; ww++) si += s_pr[ww][tid];
        g_bimp[blockIdx.x][tid] = si;
        g_bcnt[blockIdx.x][tid] = s_cnt[tid];
    }
    __threadfence();
    __syncthreads();
    if (tid == 0) {
        unsigned tk = atomicAdd(&g_done, 1u);
        s_last = (tk == gridDim.x - 1) ? 1 : 0;
    }
    __syncthreads();

    if (s_last) {
        __shared__ float red[NEXP];
        if (tid < NEXP) {
            float si = 0.0f;
            int   sc = 0;
#pragma unroll 8
            for (int b = 0; b < RBLK; b++) {
                si += *(volatile float*)&g_bimp[b][tid];
                sc += *(volatile int*)&g_bcnt[b][tid];
            }
            red[tid] = (float)NEXP * (si / (float)BATCH) *
                       ((float)sc / (float)(BATCH * TOPK));
        }
        __syncthreads();
        if (tid == 0) {
            float s = 0.0f;
#pragma unroll
            for (int i = 0; i < NEXP; i++) s += red[i];
            out[(size_t)2 * BATCH * TOPK] = s;
        }
    }
}

// ---------------------------------------------------------------------------
extern "C" void kernel_launch(void* const* d_in, const int* in_sizes, int n_in,
                              void* d_out, int out_size) {
    const float* hs  = (const float*)d_in[0];
    const float* gw  = (const float*)d_in[1];
    float*       out = (float*)d_out;

    cudaFuncSetAttribute(gemm_tc, cudaFuncAttributeMaxDynamicSharedMemorySize,
                         SM_ALLOC);
    gemm_tc<<<dim3(BATCH / BM, KSPL), 256, SM_ALLOC>>>(hs, gw);
    router_kernel<<<RBLK, RTHR>>>(out);
}

// round 6
// speedup vs baseline: 1.0726x; 1.0726x over previous
#include <cuda_runtime.h>
#include <cuda_bf16.h>
#include <cstdint>

// ---------------------------------------------------------------------------
// Problem constants
// ---------------------------------------------------------------------------
#define BATCH   8192
#define SEQ     8
#define HID     2048
#define NEXP    64
#define TOPK    8
#define ROWSTR  (SEQ * HID)

// GEMM config: BM=64, 4 warps (2M x 2N, m32n32 each), 2 CTAs/SM
#define BM      64
#define KT      64                 // k-tile (f32 elements)
#define KSPL    2
#define KHALF   (HID / KSPL)       // 1024
#define NT      (KHALF / KT)       // 16 tiles per split

// smem plane sizes (bf16, 128B per row)
#define A_PL    8192               // 64 rows x 128B
#define B_PL    8192
#define ABUF    (3 * A_PL)
#define BBUF    (3 * B_PL)
#define STAGE   (ABUF + BBUF)      // 49152
#define SM_ALLOC (2 * STAGE + 1024)   // 99328 -> 2 CTAs/SM

// Router config: 512 blocks x 512 threads (16 rows/block)
#define RBLK    512
#define RTHR    512
#define RWARPS  (RTHR / 32)        // 16

// Scratch (no allocation allowed)
__device__ float    g_partial[KSPL][BATCH * NEXP];   // 4 MB
__device__ float    g_bimp[RBLK][NEXP];
__device__ int      g_bcnt[RBLK][NEXP];
__device__ unsigned g_done;

// ---------------------------------------------------------------------------
// helpers
// ---------------------------------------------------------------------------
__device__ __forceinline__ uint32_t smem_to_u32(const void* p) {
    uint32_t a;
    asm("{ .reg .u64 t; cvta.to.shared.u64 t, %1; cvt.u32.u64 %0, t; }"
        : "=r"(a) : "l"(p));
    return a;
}
__device__ __forceinline__ void ldsm4(uint32_t* r, uint32_t addr) {
    asm volatile("ldmatrix.sync.aligned.m8n8.x4.shared.b16 {%0,%1,%2,%3}, [%4];"
                 : "=r"(r[0]), "=r"(r[1]), "=r"(r[2]), "=r"(r[3]) : "r"(addr));
}
__device__ __forceinline__ void mma16816(float* d, const uint32_t* a,
                                         const uint32_t* b) {
    asm volatile(
        "mma.sync.aligned.m16n8k16.row.col.f32.bf16.bf16.f32 "
        "{%0,%1,%2,%3}, {%4,%5,%6,%7}, {%8,%9}, {%0,%1,%2,%3};"
        : "+f"(d[0]), "+f"(d[1]), "+f"(d[2]), "+f"(d[3])
        : "r"(a[0]), "r"(a[1]), "r"(a[2]), "r"(a[3]), "r"(b[0]), "r"(b[1]));
}
__device__ __forceinline__ uint32_t pack_bf16(float lo, float hi) {
    uint32_t r;
    asm("cvt.rn.bf16x2.f32 %0, %1, %2;" : "=r"(r) : "f"(hi), "f"(lo));
    return r;
}
// fp32 -> 3x bf16 split: h + m + l reproduces x to ~2^-26 relative
__device__ __forceinline__ void split3(float x, float y,
                                       uint32_t& h, uint32_t& m, uint32_t& l) {
    h = pack_bf16(x, y);
    float hx = __uint_as_float(h << 16);
    float hy = __uint_as_float(h & 0xffff0000u);
    float rx = x - hx, ry = y - hy;
    m = pack_bf16(rx, ry);
    float mx = __uint_as_float(m << 16);
    float my = __uint_as_float(m & 0xffff0000u);
    l = pack_bf16(rx - mx, ry - my);
}
__device__ __forceinline__ void sts64(uint32_t addr, uint32_t a, uint32_t b) {
    asm volatile("st.shared.v2.b32 [%0], {%1, %2};"
                 :: "r"(addr), "r"(a), "r"(b) : "memory");
}

// ---------------------------------------------------------------------------
// Kernel 1: HMMA logits GEMM, fp32 emulated with bf16 3-split (6 products).
// D[64,64] per (m-tile, k-split). 128 threads = 4 warps = 2(M) x 2(N),
// each warp computes a 32x32 tile (maximal fragment reuse per ldmatrix).
// ---------------------------------------------------------------------------
__global__ void __launch_bounds__(128, 2)
gemm_tc(const float* __restrict__ hs, const float* __restrict__ gw) {
    extern __shared__ char smem_raw[];
    const uint32_t sb = (smem_to_u32(smem_raw) + 1023u) & ~1023u;

    const int tid  = threadIdx.x;
    const int wid  = tid >> 5;
    const int lane = tid & 31;
    const int m0   = blockIdx.x * BM;
    const int sp   = blockIdx.y;
    const int k0   = sp * KHALF;

    if (blockIdx.x == 0 && sp == 0 && tid == 0) g_done = 0u;

    // ---- f32 staging in regs: 8 float4 each for A and B ----
    float4 ar[8], br[8];
#define LOAD_A(t) do {                                                        \
    int kk = k0 + (t) * KT;                                                   \
    _Pragma("unroll")                                                         \
    for (int i = 0; i < 8; i++) {                                             \
        int lin = tid + i * 128; int row = lin >> 4; int c4 = lin & 15;       \
        ar[i] = *(const float4*)(hs + (size_t)(m0 + row) * ROWSTR + kk + c4 * 4); \
    } } while (0)
#define LOAD_B(t) do {                                                        \
    int kk = k0 + (t) * KT;                                                   \
    _Pragma("unroll")                                                         \
    for (int i = 0; i < 8; i++) {                                             \
        int lin = tid + i * 128; int row = lin >> 4; int c4 = lin & 15;       \
        br[i] = *(const float4*)(gw + (size_t)row * HID + kk + c4 * 4);       \
    } } while (0)

    LOAD_A(0); LOAD_B(0);

    // ---- per-warp ldmatrix bases (unswizzled) + swizzle masks ----
    const int wm = (wid & 1) * 32;         // warp M offset within 64
    const int wn = (wid >> 1) * 32;        // warp N offset within 64

    uint32_t abase[2], amask[2];
#pragma unroll
    for (int mt = 0; mt < 2; mt++) {
        int row = wm + mt * 16 + (lane & 15);
        abase[mt] = (uint32_t)(row * 128 + (lane >> 4) * 16);
        amask[mt] = (uint32_t)((row & 7) << 4);
    }
    uint32_t bbase[2], bmask[2];
#pragma unroll
    for (int nt = 0; nt < 2; nt++) {
        int mat = lane >> 3, r = lane & 7;
        int n  = wn + nt * 16 + (mat >> 1) * 8 + r;
        int kb = (mat & 1) * 16;
        bbase[nt] = (uint32_t)(n * 128 + kb);
        bmask[nt] = (uint32_t)((n & 7) << 4);
    }

    float acc[2][4][4];
#pragma unroll
    for (int a = 0; a < 2; a++)
#pragma unroll
        for (int b = 0; b < 4; b++)
#pragma unroll
            for (int c = 0; c < 4; c++) acc[a][b][c] = 0.0f;

    const int pa[6] = {0, 0, 1, 0, 2, 1};   // hh, hm, mh, hl, lh, mm
    const int pb[6] = {0, 1, 0, 2, 0, 1};

    for (int t = 0; t < NT; t++) {
        const uint32_t stg   = sb + (uint32_t)(t & 1) * STAGE;
        const uint32_t aBase = stg;
        const uint32_t bBase = stg + ABUF;

        // convert + swizzled store: A (8 float4 -> 3 planes)
#pragma unroll
        for (int i = 0; i < 8; i++) {
            int lin = tid + i * 128; int row = lin >> 4; int c4 = lin & 15;
            uint32_t off = (uint32_t)(row * 128 + c4 * 8);
            uint32_t sw  = off ^ ((off >> 3) & 0x70u);
            uint32_t h0, mm0, l0, h1, mm1, l1;
            split3(ar[i].x, ar[i].y, h0, mm0, l0);
            split3(ar[i].z, ar[i].w, h1, mm1, l1);
            sts64(aBase + sw,            h0,  h1);
            sts64(aBase + A_PL + sw,     mm0, mm1);
            sts64(aBase + 2 * A_PL + sw, l0,  l1);
        }
        // convert + swizzled store: B
#pragma unroll
        for (int i = 0; i < 8; i++) {
            int lin = tid + i * 128; int row = lin >> 4; int c4 = lin & 15;
            uint32_t off = (uint32_t)(row * 128 + c4 * 8);
            uint32_t sw  = off ^ ((off >> 3) & 0x70u);
            uint32_t h0, mm0, l0, h1, mm1, l1;
            split3(br[i].x, br[i].y, h0, mm0, l0);
            split3(br[i].z, br[i].w, h1, mm1, l1);
            sts64(bBase + sw,            h0,  h1);
            sts64(bBase + B_PL + sw,     mm0, mm1);
            sts64(bBase + 2 * B_PL + sw, l0,  l1);
        }
        __syncthreads();

        // prefetch next tile's f32 (overlaps with MMA below)
        if (t + 1 < NT) { LOAD_A(t + 1); LOAD_B(t + 1); }

        // compute: 4 k16 chunks x (12 ldmatrix.x4 + 48 mma) per warp
#pragma unroll
        for (int kc = 0; kc < 4; kc++) {
            uint32_t af[3][2][4];
            uint32_t bf[3][2][4];
#pragma unroll
            for (int p = 0; p < 3; p++) {
#pragma unroll
                for (int mt = 0; mt < 2; mt++)
                    ldsm4(af[p][mt],
                          aBase + p * A_PL + ((abase[mt] + kc * 32) ^ amask[mt]));
#pragma unroll
                for (int nt = 0; nt < 2; nt++)
                    ldsm4(bf[p][nt],
                          bBase + p * B_PL + ((bbase[nt] + kc * 32) ^ bmask[nt]));
            }
#pragma unroll
            for (int pr = 0; pr < 6; pr++) {
#pragma unroll
                for (int mt = 0; mt < 2; mt++) {
#pragma unroll
                    for (int nt = 0; nt < 2; nt++) {
                        mma16816(acc[mt][nt * 2 + 0], af[pa[pr]][mt], &bf[pb[pr]][nt][0]);
                        mma16816(acc[mt][nt * 2 + 1], af[pa[pr]][mt], &bf[pb[pr]][nt][2]);
                    }
                }
            }
        }
        __syncthreads();
    }

    // ---- epilogue: warp writes its 32x32 f32 tile to split partials ----
    const int gr = m0 + wm + (lane >> 2);
    const int gc = wn + (lane & 3) * 2;
#pragma unroll
    for (int mt = 0; mt < 2; mt++) {
#pragma unroll
        for (int n8 = 0; n8 < 4; n8++) {
            int row = gr + mt * 16;
            int col = gc + n8 * 8;
            *(float2*)&g_partial[sp][(size_t)row * NEXP + col] =
                make_float2(acc[mt][n8][0], acc[mt][n8][1]);
            *(float2*)&g_partial[sp][(size_t)(row + 8) * NEXP + col] =
                make_float2(acc[mt][n8][2], acc[mt][n8][3]);
        }
    }
#undef LOAD_A
#undef LOAD_B
}

// ---------------------------------------------------------------------------
// Kernel 2: warp-per-row softmax + top-8 + weights. Importance/load reduced
// per-block into private global slots; last block (ticket) reduces the 512
// partials with ALL 512 threads (MLP-rich), then emits aux_loss.
// ---------------------------------------------------------------------------
__global__ void __launch_bounds__(RTHR)
router_kernel(float* __restrict__ out) {
    __shared__ float s_pr[RWARPS][NEXP];   // 4KB
    __shared__ int   s_cnt[NEXP];
    __shared__ int   s_last;
    const int tid  = threadIdx.x;
    const int lane = tid & 31;
    const int w    = tid >> 5;
    if (tid < NEXP) s_cnt[tid] = 0;
    __syncthreads();

    const int row = blockIdx.x * RWARPS + w;

    // sum split-K partials; lane owns experts lane, lane+32
    const float* p0p = &g_partial[0][(size_t)row * NEXP];
    const float* p1p = &g_partial[1][(size_t)row * NEXP];
    float l0 = p0p[lane] + p1p[lane];
    float l1 = p0p[lane + 32] + p1p[lane + 32];

    // softmax over 64
    float m = fmaxf(l0, l1);
#pragma unroll
    for (int off = 16; off; off >>= 1)
        m = fmaxf(m, __shfl_xor_sync(0xffffffffu, m, off));
    float p0 = __expf(l0 - m);
    float p1 = __expf(l1 - m);
    float sm = p0 + p1;
#pragma unroll
    for (int off = 16; off; off >>= 1)
        sm += __shfl_xor_sync(0xffffffffu, sm, off);
    float inv = 1.0f / sm;
    p0 *= inv;
    p1 *= inv;

    s_pr[w][lane]      = p0;
    s_pr[w][lane + 32] = p1;

    // top-8 via iterated warp argmax (tie -> smaller index)
    bool sel0 = false, sel1 = false;
    float wsum = 0.0f, myv = 0.0f;
    int myi = 0;
#pragma unroll
    for (int it = 0; it < TOPK; it++) {
        float cv = sel0 ? -1.0f : p0;
        int   ci = lane;
        if (!sel1 && p1 > cv) { cv = p1; ci = lane + 32; }
#pragma unroll
        for (int off = 16; off; off >>= 1) {
            float ov = __shfl_xor_sync(0xffffffffu, cv, off);
            int   oi = __shfl_xor_sync(0xffffffffu, ci, off);
            if (ov > cv || (ov == cv && oi < ci)) { cv = ov; ci = oi; }
        }
        wsum += cv;
        if (ci == lane)           sel0 = true;
        else if (ci == lane + 32) sel1 = true;
        if (lane == it) { myv = cv; myi = ci; }
        if (lane == 0)  atomicAdd(&s_cnt[ci], 1);
    }

    float invw = 1.0f / fmaxf(wsum, 1e-8f);
    if (lane < TOPK) {
        out[(size_t)row * TOPK + lane] = (float)myi;
        out[(size_t)BATCH * TOPK + (size_t)row * TOPK + lane] = myv * invw;
    }

    __syncthreads();

    // block partials: expert e summed over 16 warps (plain smem reads)
    if (tid < NEXP) {
        float si = 0.0f;
#pragma unroll
        for (int ww = 0; ww < RWARPS; ww++) si += s_pr[ww][tid];
        g_bimp[blockIdx.x][tid] = si;
        g_bcnt[blockIdx.x][tid] = s_cnt[tid];
        __threadfence();
    }
    __syncthreads();
    if (tid == 0) {
        unsigned tk = atomicAdd(&g_done, 1u);
        s_last = (tk == gridDim.x - 1) ? 1 : 0;
    }
    __syncthreads();

    if (s_last) {
        // parallel tail: 512 threads = 8 chunks x 64 experts
        __shared__ float s_ri[8][NEXP];
        __shared__ int   s_rc[8][NEXP];
        const int e  = tid & 63;
        const int ch = tid >> 6;            // 0..7
        float si = 0.0f;
        int   sc = 0;
#pragma unroll 8
        for (int b = ch * (RBLK / 8); b < (ch + 1) * (RBLK / 8); b++) {
            si += *(volatile float*)&g_bimp[b][e];
            sc += *(volatile int*)&g_bcnt[b][e];
        }
        s_ri[ch][e] = si;
        s_rc[ch][e] = sc;
        __syncthreads();
        if (tid < NEXP) {
            float ti = 0.0f;
            int   tc = 0;
#pragma unroll
            for (int c = 0; c < 8; c++) { ti += s_ri[c][tid]; tc += s_rc[c][tid]; }
            s_ri[0][tid] = (float)NEXP * (ti / (float)BATCH) *
                           ((float)tc / (float)(BATCH * TOPK));
        }
        __syncthreads();
        if (tid == 0) {
            float s = 0.0f;
#pragma unroll
            for (int i = 0; i < NEXP; i++) s += s_ri[0][i];
            out[(size_t)2 * BATCH * TOPK] = s;
        }
    }
}

// ---------------------------------------------------------------------------
extern "C" void kernel_launch(void* const* d_in, const int* in_sizes, int n_in,
                              void* d_out, int out_size) {
    const float* hs  = (const float*)d_in[0];
    const float* gw  = (const float*)d_in[1];
    float*       out = (float*)d_out;

    cudaFuncSetAttribute(gemm_tc, cudaFuncAttributeMaxDynamicSharedMemorySize,
                         SM_ALLOC);
    gemm_tc<<<dim3(BATCH / BM, KSPL), 128, SM_ALLOC>>>(hs, gw);
    router_kernel<<<RBLK, RTHR>>>(out);
}

// round 8
// speedup vs baseline: 1.1468x; 1.0691x over previous
#include <cuda_runtime.h>
#include <cuda_bf16.h>
#include <cstdint>

// ---------------------------------------------------------------------------
// Problem constants
// ---------------------------------------------------------------------------
#define BATCH   8192
#define SEQ     8
#define HID     2048
#define NEXP    64
#define TOPK    8
#define ROWSTR  (SEQ * HID)

// GEMM config: BM=64, split-K=2 (256 CTAs = one wave at 2 CTAs/SM),
// warp-specialized: warps 0-3 consumers (m32n32 each), warps 4-7 producers.
#define BM      64
#define KT      64                 // k-tile (f32 elements)
#define KSPL    2
#define KHALF   (HID / KSPL)       // 1024
#define NT      (KHALF / KT)       // 16 tiles per split

// smem plane sizes (bf16, 128B per row)
#define A_PL    8192               // 64 rows x 128B
#define B_PL    8192
#define ABUF    (3 * A_PL)
#define BBUF    (3 * B_PL)
#define STAGE   (ABUF + BBUF)      // 49152
#define SM_ALLOC (2 * STAGE + 1024)   // 99328 -> 2 CTAs/SM

// Router config: 512 blocks x 512 threads (16 rows/block)
#define RBLK    512
#define RTHR    512
#define RWARPS  (RTHR / 32)        // 16

// Scratch (no allocation allowed)
__device__ float    g_partial[KSPL][BATCH * NEXP];  // 4 MB
__device__ uint32_t g_bsplit[3 * NEXP * HID / 2];   // 3 bf16 planes of gate_w
__device__ float    g_bimp[RBLK][NEXP];
__device__ int      g_bcnt[RBLK][NEXP];
__device__ unsigned g_done;

// ---------------------------------------------------------------------------
// helpers
// ---------------------------------------------------------------------------
__device__ __forceinline__ uint32_t smem_to_u32(const void* p) {
    uint32_t a;
    asm("{ .reg .u64 t; cvta.to.shared.u64 t, %1; cvt.u32.u64 %0, t; }"
        : "=r"(a) : "l"(p));
    return a;
}
__device__ __forceinline__ void ldsm4(uint32_t* r, uint32_t addr) {
    asm volatile("ldmatrix.sync.aligned.m8n8.x4.shared.b16 {%0,%1,%2,%3}, [%4];"
                 : "=r"(r[0]), "=r"(r[1]), "=r"(r[2]), "=r"(r[3]) : "r"(addr));
}
__device__ __forceinline__ void mma16816(float* d, const uint32_t* a,
                                         const uint32_t* b) {
    asm volatile(
        "mma.sync.aligned.m16n8k16.row.col.f32.bf16.bf16.f32 "
        "{%0,%1,%2,%3}, {%4,%5,%6,%7}, {%8,%9}, {%0,%1,%2,%3};"
        : "+f"(d[0]), "+f"(d[1]), "+f"(d[2]), "+f"(d[3])
        : "r"(a[0]), "r"(a[1]), "r"(a[2]), "r"(a[3]), "r"(b[0]), "r"(b[1]));
}
__device__ __forceinline__ uint32_t pack_bf16(float lo, float hi) {
    uint32_t r;
    asm("cvt.rn.bf16x2.f32 %0, %1, %2;" : "=r"(r) : "f"(hi), "f"(lo));
    return r;
}
// fp32 -> 3x bf16 split: h + m + l reproduces x to ~2^-26 relative
__device__ __forceinline__ void split3(float x, float y,
                                       uint32_t& h, uint32_t& m, uint32_t& l) {
    h = pack_bf16(x, y);
    float hx = __uint_as_float(h << 16);
    float hy = __uint_as_float(h & 0xffff0000u);
    float rx = x - hx, ry = y - hy;
    m = pack_bf16(rx, ry);
    float mx = __uint_as_float(m << 16);
    float my = __uint_as_float(m & 0xffff0000u);
    l = pack_bf16(rx - mx, ry - my);
}
__device__ __forceinline__ void sts64(uint32_t addr, uint32_t a, uint32_t b) {
    asm volatile("st.shared.v2.b32 [%0], {%1, %2};"
                 :: "r"(addr), "r"(a), "r"(b) : "memory");
}
__device__ __forceinline__ void sts128(uint32_t addr, uint4 v) {
    asm volatile("st.shared.v4.b32 [%0], {%1, %2, %3, %4};"
                 :: "r"(addr), "r"(v.x), "r"(v.y), "r"(v.z), "r"(v.w) : "memory");
}
// named producer/consumer barriers (256 = all threads of the CTA)
#define BAR_SYNC(id)   asm volatile("bar.sync %0, 256;"   :: "r"(id) : "memory")
#define BAR_ARRIVE(id) asm volatile("bar.arrive %0, 256;" :: "r"(id) : "memory")

__device__ __forceinline__ int redux_max_s32(int v) {
    int r;
    asm("redux.sync.max.s32 %0, %1, 0xffffffff;" : "=r"(r) : "r"(v));
    return r;
}
__device__ __forceinline__ unsigned redux_max_u32(unsigned v) {
    unsigned r;
    asm("redux.sync.max.u32 %0, %1, 0xffffffff;" : "=r"(r) : "r"(v));
    return r;
}
// order-preserving float <-> u32 (for max over possibly-negative logits)
__device__ __forceinline__ unsigned fenc(float f) {
    int b = __float_as_int(f);
    return (unsigned)(b ^ ((b >> 31) | 0x80000000));
}
__device__ __forceinline__ float fdec(unsigned u) {
    int b = (u & 0x80000000u) ? (int)(u ^ 0x80000000u) : (int)~u;
    return __int_as_float(b);
}

// ---------------------------------------------------------------------------
// Kernel 0: pre-split gate_w into 3 bf16 planes (once per launch, L2-resident)
// ---------------------------------------------------------------------------
__global__ void __launch_bounds__(256)
bsplit_kernel(const float* __restrict__ gw) {
    int g = blockIdx.x * 256 + threadIdx.x;       // 0..16383, 8 floats each
    const float2* src = (const float2*)gw + (size_t)g * 4;
#pragma unroll
    for (int j = 0; j < 4; j++) {
        float2 v = src[j];
        uint32_t h, m, l;
        split3(v.x, v.y, h, m, l);
        int pi = g * 4 + j;
        g_bsplit[pi]             = h;
        g_bsplit[65536 + pi]     = m;
        g_bsplit[2 * 65536 + pi] = l;
    }
}

// ---------------------------------------------------------------------------
// Kernel 1: warp-specialized HMMA logits GEMM (bf16 3-split, 6 products).
// Producers (warps 4-7): LDG A f32 -> split3 -> STS; LDG pre-split B -> STS.
// Consumers (warps 0-3): LDSM + MMA, m32n32 per warp.
// Accumulation order identical to the R6-passing kernel (split-K=2).
// ---------------------------------------------------------------------------
__global__ void __launch_bounds__(256, 1)
gemm_tc(const float* __restrict__ hs, const float* __restrict__ gw) {
    extern __shared__ char smem_raw[];
    const uint32_t sb = (smem_to_u32(smem_raw) + 1023u) & ~1023u;

    const int tid  = threadIdx.x;
    const int wid  = tid >> 5;
    const int lane = tid & 31;
    const int m0   = blockIdx.x * BM;
    const int sp   = blockIdx.y;
    const int k0   = sp * KHALF;

    if (blockIdx.x == 0 && sp == 0 && tid == 0) g_done = 0u;

    if (wid < 4) {
        // =================== CONSUMER ===================
        const int wm = (wid & 1) * 32;
        const int wn = (wid >> 1) * 32;

        uint32_t abase[2], amask[2];
#pragma unroll
        for (int mt = 0; mt < 2; mt++) {
            int row = wm + mt * 16 + (lane & 15);
            abase[mt] = (uint32_t)(row * 128 + (lane >> 4) * 16);
            amask[mt] = (uint32_t)((row & 7) << 4);
        }
        uint32_t bbase[2], bmask[2];
#pragma unroll
        for (int nt = 0; nt < 2; nt++) {
            int mat = lane >> 3, r = lane & 7;
            int n  = wn + nt * 16 + (mat >> 1) * 8 + r;
            int kb = (mat & 1) * 16;
            bbase[nt] = (uint32_t)(n * 128 + kb);
            bmask[nt] = (uint32_t)((n & 7) << 4);
        }

        float acc[2][4][4];
#pragma unroll
        for (int a = 0; a < 2; a++)
#pragma unroll
            for (int b = 0; b < 4; b++)
#pragma unroll
                for (int c = 0; c < 4; c++) acc[a][b][c] = 0.0f;

        const int pa[6] = {0, 0, 1, 0, 2, 1};   // hh, hm, mh, hl, lh, mm
        const int pb[6] = {0, 1, 0, 2, 0, 1};

        for (int t = 0; t < NT; t++) {
            const int buf = t & 1;
            const uint32_t aBase = sb + (uint32_t)buf * STAGE;
            const uint32_t bBase = aBase + ABUF;

            BAR_SYNC(1 + buf);          // wait tile full

#pragma unroll
            for (int kc = 0; kc < 4; kc++) {
                uint32_t af[3][2][4];
                uint32_t bf[3][2][4];
#pragma unroll
                for (int p = 0; p < 3; p++) {
#pragma unroll
                    for (int mt = 0; mt < 2; mt++)
                        ldsm4(af[p][mt],
                              aBase + p * A_PL + ((abase[mt] + kc * 32) ^ amask[mt]));
#pragma unroll
                    for (int nt = 0; nt < 2; nt++)
                        ldsm4(bf[p][nt],
                              bBase + p * B_PL + ((bbase[nt] + kc * 32) ^ bmask[nt]));
                }
#pragma unroll
                for (int pr = 0; pr < 6; pr++) {
#pragma unroll
                    for (int mt = 0; mt < 2; mt++) {
#pragma unroll
                        for (int nt = 0; nt < 2; nt++) {
                            mma16816(acc[mt][nt * 2 + 0], af[pa[pr]][mt], &bf[pb[pr]][nt][0]);
                            mma16816(acc[mt][nt * 2 + 1], af[pa[pr]][mt], &bf[pb[pr]][nt][2]);
                        }
                    }
                }
            }
            if (t + 2 < NT) BAR_ARRIVE(3 + buf);   // tile free
        }

        // epilogue: warp writes its 32x32 f32 tile to split partials
        const int gr = m0 + wm + (lane >> 2);
        const int gc = wn + (lane & 3) * 2;
#pragma unroll
        for (int mt = 0; mt < 2; mt++) {
#pragma unroll
            for (int n8 = 0; n8 < 4; n8++) {
                int row = gr + mt * 16;
                int col = gc + n8 * 8;
                *(float2*)&g_partial[sp][(size_t)row * NEXP + col] =
                    make_float2(acc[mt][n8][0], acc[mt][n8][1]);
                *(float2*)&g_partial[sp][(size_t)(row + 8) * NEXP + col] =
                    make_float2(acc[mt][n8][2], acc[mt][n8][3]);
            }
        }
    } else {
        // =================== PRODUCER ===================
        const int wt = tid & 127;     // 0..127

        float4 ar[8], arn[8];
#define LOAD_A(t, dst) do {                                                   \
    int kk = k0 + (t) * KT;                                                   \
    _Pragma("unroll")                                                         \
    for (int i = 0; i < 8; i++) {                                             \
        int lin = wt + i * 128; int row = lin >> 4; int c4 = lin & 15;        \
        (dst)[i] = *(const float4*)(hs + (size_t)(m0 + row) * ROWSTR + kk + c4 * 4); \
    } } while (0)

        LOAD_A(0, ar);
        const __nv_bfloat16* bsp = (const __nv_bfloat16*)g_bsplit;

        for (int t = 0; t < NT; t++) {
            const int buf = t & 1;
            const uint32_t aBase = sb + (uint32_t)buf * STAGE;
            const uint32_t bBase = aBase + ABUF;
            const int kk = k0 + t * KT;

            // prefetch next A tile (DRAM latency hidden behind everything)
            if (t + 1 < NT) LOAD_A(t + 1, arn);

            // B tile: 3 planes x 64 rows x 8 chunks(16B) = 1536 / 128 thr = 12
            uint4 bq[12];
#pragma unroll
            for (int j = 0; j < 12; j++) {
                int lin = wt + j * 128;
                int p = lin >> 9, r = (lin >> 3) & 63, ch = lin & 7;
                bq[j] = *(const uint4*)(bsp + (size_t)p * (NEXP * HID)
                                        + r * HID + kk + ch * 8);
            }

            if (t >= 2) BAR_SYNC(3 + buf);   // wait tile free

            // convert + swizzled store: A
#pragma unroll
            for (int i = 0; i < 8; i++) {
                int lin = wt + i * 128; int row = lin >> 4; int c4 = lin & 15;
                uint32_t off = (uint32_t)(row * 128 + c4 * 8);
                uint32_t sw  = off ^ ((off >> 3) & 0x70u);
                uint32_t h0, mm0, l0, h1, mm1, l1;
                split3(ar[i].x, ar[i].y, h0, mm0, l0);
                split3(ar[i].z, ar[i].w, h1, mm1, l1);
                sts64(aBase + sw,            h0,  h1);
                sts64(aBase + A_PL + sw,     mm0, mm1);
                sts64(aBase + 2 * A_PL + sw, l0,  l1);
            }
            // store pre-split B (swizzled 16B chunks; XOR mask is constant
            // across each 16B chunk so sts128 stays layout-exact)
#pragma unroll
            for (int j = 0; j < 12; j++) {
                int lin = wt + j * 128;
                int p = lin >> 9, r = (lin >> 3) & 63, ch = lin & 7;
                uint32_t off = (uint32_t)(r * 128 + ch * 16);
                uint32_t sw  = off ^ ((off >> 3) & 0x70u);
                sts128(bBase + p * B_PL + sw, bq[j]);
            }
            BAR_ARRIVE(1 + buf);             // tile full

#pragma unroll
            for (int i = 0; i < 8; i++) ar[i] = arn[i];
        }
#undef LOAD_A
    }
}

// ---------------------------------------------------------------------------
// Kernel 2: warp-per-row softmax + top-8 (redux.sync argmax) + weights.
// Per-block partials -> private global slots; last block reduces (parallel).
// ---------------------------------------------------------------------------
__global__ void __launch_bounds__(RTHR)
router_kernel(float* __restrict__ out) {
    __shared__ float s_pr[RWARPS][NEXP];
    __shared__ int   s_cnt[NEXP];
    __shared__ int   s_last;
    const int tid  = threadIdx.x;
    const int lane = tid & 31;
    const int w    = tid >> 5;
    if (tid < NEXP) s_cnt[tid] = 0;
    __syncthreads();

    const int row = blockIdx.x * RWARPS + w;

    // sum split-K partials (identical order to R6-passing kernel)
    const float* p0p = &g_partial[0][(size_t)row * NEXP];
    const float* p1p = &g_partial[1][(size_t)row * NEXP];
    float l0 = p0p[lane] + p1p[lane];
    float l1 = p0p[lane + 32] + p1p[lane + 32];

    // softmax over 64 (max via order-preserving redux)
    unsigned em = redux_max_u32(fenc(fmaxf(l0, l1)));
    float m = fdec(em);
    float p0 = __expf(l0 - m);
    float p1 = __expf(l1 - m);
    float sm = p0 + p1;
#pragma unroll
    for (int off = 16; off; off >>= 1)
        sm += __shfl_xor_sync(0xffffffffu, sm, off);
    float inv = 1.0f / sm;
    p0 *= inv;
    p1 *= inv;

    s_pr[w][lane]      = p0;
    s_pr[w][lane + 32] = p1;

    // top-8: probs >= 0 so f32 bits are s32-monotonic -> redux.max.s32
    const int NEG1 = 0xBF800000;   // -1.0f
    int b0i = __float_as_int(p0);
    int b1i = __float_as_int(p1);
    bool sel0 = false, sel1 = false;
    float wsum = 0.0f, myv = 0.0f;
    int myi = 0;
#pragma unroll
    for (int it = 0; it < TOPK; it++) {
        int c0 = sel0 ? NEG1 : b0i;
        int c1 = sel1 ? NEG1 : b1i;
        int mv = redux_max_s32(c0 > c1 ? c0 : c1);
        unsigned q0 = __ballot_sync(0xffffffffu, c0 == mv);
        unsigned q1 = __ballot_sync(0xffffffffu, c1 == mv);
        int idx = q0 ? (__ffs(q0) - 1) : (__ffs(q1) + 31);
        float fv = __int_as_float(mv);
        wsum += fv;
        if (idx == lane)           sel0 = true;
        else if (idx == lane + 32) sel1 = true;
        if (lane == it) { myv = fv; myi = idx; }
        if (lane == 0)  atomicAdd(&s_cnt[idx], 1);
    }

    float invw = 1.0f / fmaxf(wsum, 1e-8f);
    if (lane < TOPK) {
        out[(size_t)row * TOPK + lane] = (float)myi;
        out[(size_t)BATCH * TOPK + (size_t)row * TOPK + lane] = myv * invw;
    }

    __syncthreads();

    // block partials -> private global slots
    if (tid < NEXP) {
        float si = 0.0f;
#pragma unroll
        for (int ww = 0; ww < RWARPS; ww++) si += s_pr[ww][tid];
        g_bimp[blockIdx.x][tid] = si;
        g_bcnt[blockIdx.x][tid] = s_cnt[tid];
        __threadfence();
    }
    __syncthreads();
    if (tid == 0) {
        unsigned tk = atomicAdd(&g_done, 1u);
        s_last = (tk == gridDim.x - 1) ? 1 : 0;
    }
    __syncthreads();

    if (s_last) {
        // parallel tail: 512 threads = 8 chunks x 64 experts
        __shared__ float s_ri[8][NEXP];
        __shared__ int   s_rc[8][NEXP];
        const int e  = tid & 63;
        const int ch = tid >> 6;            // 0..7
        float si = 0.0f;
        int   sc = 0;
#pragma unroll 8
        for (int b = ch * (RBLK / 8); b < (ch + 1) * (RBLK / 8); b++) {
            si += *(volatile float*)&g_bimp[b][e];
            sc += *(volatile int*)&g_bcnt[b][e];
        }
        s_ri[ch][e] = si;
        s_rc[ch][e] = sc;
        __syncthreads();
        if (tid < NEXP) {
            float ti = 0.0f;
            int   tc = 0;
#pragma unroll
            for (int c = 0; c < 8; c++) { ti += s_ri[c][tid]; tc += s_rc[c][tid]; }
            s_ri[0][tid] = (float)NEXP * (ti / (float)BATCH) *
                           ((float)tc / (float)(BATCH * TOPK));
        }
        __syncthreads();
        if (tid == 0) {
            float s = 0.0f;
#pragma unroll
            for (int i = 0; i < NEXP; i++) s += s_ri[0][i];
            out[(size_t)2 * BATCH * TOPK] = s;
        }
    }
}

// ---------------------------------------------------------------------------
extern "C" void kernel_launch(void* const* d_in, const int* in_sizes, int n_in,
                              void* d_out, int out_size) {
    const float* hs  = (const float*)d_in[0];
    const float* gw  = (const float*)d_in[1];
    float*       out = (float*)d_out;

    cudaFuncSetAttribute(gemm_tc, cudaFuncAttributeMaxDynamicSharedMemorySize,
                         SM_ALLOC);
    bsplit_kernel<<<64, 256>>>(gw);
    gemm_tc<<<dim3(BATCH / BM, KSPL), 256, SM_ALLOC>>>(hs, gw);
    router_kernel<<<RBLK, RTHR>>>(out);
}